// round 13
// baseline (speedup 1.0000x reference)
#include <cuda_runtime.h>
#include <cuda_bf16.h>
#include <cstdint>

// ---------------------------------------------------------------------------
// RecurrentGraphNeuralNet v12:
//   prep   : fused zero(agg,deg) + dtype detect + hi/lo weight image (1 launch)
//   scatter: v9 4-edges/thread red.global.v4 (at LTS floor, unchanged)
//   update : HMMA bf16 split-precision, K split in 2 halves, TWO cp.async
//            weight waves (W0 | W1+Wp), no trailing syncs after 2nd GEMM.
// ---------------------------------------------------------------------------

#define MAXN 100000

__device__ float g_agg[(long long)MAXN * 64];
__device__ float g_deg[MAXN];
__device__ int   g_is64;

// Weight image (per-half tiles, stride 72 bf16):
// [W0hi 9216][W0lo 9216][bs 256][bps 128][pad->18816]
// [W1hi 9216][W1lo 9216][Wph 4608][Wpl 4608]   total 46464
#define IMG_W0   0
#define IMG_BS   18432
#define IMG_BPS  18688
#define IMG_W1   18816
#define IMG_WP   37248
#define IMG_BYTES 46464
__device__ __align__(128) unsigned char g_wimg[IMG_BYTES];

// ---------------------------------------------------------------------------
__device__ __forceinline__ uint32_t smem_u32(const void* p) {
    uint32_t a;
    asm("{ .reg .u64 t; cvta.to.shared.u64 t, %1; cvt.u32.u64 %0, t; }"
        : "=r"(a) : "l"(p));
    return a;
}
__device__ __forceinline__ void ldsm_x4(uint32_t addr, uint32_t r[4]) {
    asm volatile("ldmatrix.sync.aligned.m8n8.x4.shared.b16 {%0,%1,%2,%3}, [%4];"
        : "=r"(r[0]), "=r"(r[1]), "=r"(r[2]), "=r"(r[3]) : "r"(addr));
}
__device__ __forceinline__ void mma16816(float d[4], const uint32_t a[4],
                                         const uint32_t b[2]) {
    asm volatile(
        "mma.sync.aligned.m16n8k16.row.col.f32.bf16.bf16.f32 "
        "{%0,%1,%2,%3}, {%4,%5,%6,%7}, {%8,%9}, {%0,%1,%2,%3};"
        : "+f"(d[0]), "+f"(d[1]), "+f"(d[2]), "+f"(d[3])
        : "r"(a[0]), "r"(a[1]), "r"(a[2]), "r"(a[3]), "r"(b[0]), "r"(b[1]));
}
__device__ __forceinline__ void cp_async16(uint32_t dst, const void* src) {
    asm volatile("cp.async.cg.shared.global [%0], [%1], 16;"
                 :: "r"(dst), "l"(src) : "memory");
}
__device__ __forceinline__ uint32_t pack_bf2(float lo, float hi) {
    __nv_bfloat162 h = __floats2bfloat162_rn(lo, hi);
    return *reinterpret_cast<uint32_t*>(&h);
}
__device__ __forceinline__ float bf_lo(uint32_t w) {
    __nv_bfloat16 h = *reinterpret_cast<__nv_bfloat16*>(&w);
    return __bfloat162float(h);
}
__device__ __forceinline__ float bf_hi(uint32_t w) {
    uint32_t s = w >> 16;
    __nv_bfloat16 h = *reinterpret_cast<__nv_bfloat16*>(&s);
    return __bfloat162float(h);
}

// SMEM layout (bytes): A hi/lo (stride 72 bf16 = 144B rows), one 27.6KB
// weight slot (W-half hi/lo, later W1 hi/lo + Wp hi/lo), biases.
#define SO_AHI   0            // 18432
#define SO_ALO   18432        // 18432
#define SO_W     36864        // 27648 slot
#define SO_BS    64512        // 256
#define SO_BPS   64768        // 128
#define SMEM_BYTES 64896      // x3 blocks = 194688 <= 227KB/SM

// ---------------------------------------------------------------------------
// Fused prep: zero agg/deg, detect index dtype, build weight image.
__global__ void prep_kernel(const void* ei, int E, int N, int zero_blocks,
                            const float* __restrict__ W,
                            const float* __restrict__ Bm,
                            const float* __restrict__ Wp,
                            const float* __restrict__ b,
                            const float* __restrict__ bp)
{
    if ((int)blockIdx.x < zero_blocks) {
        long long i = (long long)blockIdx.x * 256 + threadIdx.x;
        long long nagg4 = (long long)N * 16;
        if (i < nagg4)
            *reinterpret_cast<float4*>(g_agg + i * 4) =
                make_float4(0.f, 0.f, 0.f, 0.f);
        if (i < N) g_deg[i] = 0.f;
        return;
    }
    int i = ((int)blockIdx.x - zero_blocks) * 256 + threadIdx.x;
    if (i == 0) {                         // dtype detect
        const long long* p = (const long long*)ei;
        int is64 = 1;
        #pragma unroll
        for (int k = 0; k < 8; k++) {
            long long v = p[k];
            if (v < 0 || v >= (long long)N) { is64 = 0; break; }
        }
        g_is64 = is64;
    }
    if (i < 8192) {                       // Wt[n][k], split in k-halves
        int n = i & 63, kg = i >> 6;
        float wv = (kg < 64) ? W[kg * 64 + n] : Bm[(kg - 64) * 64 + n];
        __nv_bfloat16 whi = __float2bfloat16(wv);
        __nv_bfloat16 wlo = __float2bfloat16(wv - __bfloat162float(whi));
        int half = kg >> 6, kl = kg & 63;
        uint32_t base = half ? IMG_W1 : IMG_W0;
        uint32_t off = base + (uint32_t)(n * 72 + kl) * 2;
        *reinterpret_cast<__nv_bfloat16*>(g_wimg + off)        = whi;
        *reinterpret_cast<__nv_bfloat16*>(g_wimg + off + 9216) = wlo;
    } else if (i < 10240) {               // WpT[p][k], stride 72
        int j = i - 8192;
        int p = j & 31, k = j >> 5;
        float wv = Wp[k * 32 + p];
        __nv_bfloat16 whi = __float2bfloat16(wv);
        __nv_bfloat16 wlo = __float2bfloat16(wv - __bfloat162float(whi));
        uint32_t off = IMG_WP + (uint32_t)(p * 72 + k) * 2;
        *reinterpret_cast<__nv_bfloat16*>(g_wimg + off)        = whi;
        *reinterpret_cast<__nv_bfloat16*>(g_wimg + off + 4608) = wlo;
    } else if (i < 10304) {
        int j = i - 10240;
        *reinterpret_cast<float*>(g_wimg + IMG_BS + j * 4) = b[j];
    } else if (i < 10336) {
        int j = i - 10304;
        *reinterpret_cast<float*>(g_wimg + IMG_BPS + j * 4) = bp[j];
    }
}

// ---------------------------------------------------------------------------
// Scatter (v9, at LTS floor): 4 edges/thread, batched phases, red.global.v4.
__global__ __launch_bounds__(256) void scatter_kernel(
    const float* __restrict__ x, const void* __restrict__ ei_raw, int E, int Q)
{
    long long idx = (long long)blockIdx.x * blockDim.x + threadIdx.x;
    long long total = (long long)Q * 16;
    if (idx >= total) return;

    const int is64 = g_is64;
    const int e0 = (int)(idx >> 4);
    const int f4 = ((int)idx & 15) * 4;

    int s[4], d[4];
    bool ok[4];
    #pragma unroll
    for (int j = 0; j < 4; j++) {
        int e = e0 + j * Q;
        ok[j] = (e < E);
        s[j] = 0; d[j] = 0;
        if (ok[j]) {
            if (is64) {
                const long long* ei = (const long long*)ei_raw;
                s[j] = (int)__ldg(ei + e);
                d[j] = (int)__ldg(ei + (long long)E + e);
            } else {
                const int* ei = (const int*)ei_raw;
                s[j] = __ldg(ei + e);
                d[j] = __ldg(ei + E + e);
            }
        }
    }

    float4 v[4];
    #pragma unroll
    for (int j = 0; j < 4; j++) {
        v[j] = make_float4(0.f, 0.f, 0.f, 0.f);
        if (ok[j])
            v[j] = *reinterpret_cast<const float4*>(x + (long long)s[j] * 64 + f4);
    }

    #pragma unroll
    for (int j = 0; j < 4; j++) {
        if (ok[j]) {
            float* dst = g_agg + (long long)d[j] * 64 + f4;
            asm volatile("red.global.add.v4.f32 [%0], {%1, %2, %3, %4};"
                         :: "l"(dst), "f"(v[j].x), "f"(v[j].y), "f"(v[j].z), "f"(v[j].w)
                         : "memory");
        }
    }

    if (f4 == 0) {
        #pragma unroll
        for (int j = 0; j < 4; j++)
            if (ok[j]) atomicAdd(&g_deg[d[j]], 1.0f);
    }
}

// ---------------------------------------------------------------------------
// Update v12: 128 nodes/block, 256 threads, 2 k-halves, 2 cp.async waves,
// no syncs after the second GEMM. 3 blocks/SM.
__global__ __launch_bounds__(256, 3) void update_kernel(
    const float* __restrict__ u, float* __restrict__ out, int N)
{
    extern __shared__ char smem[];
    const uint32_t sb = smem_u32(smem);
    const int t = threadIdx.x;
    const int l = t & 31;
    const int w = t >> 5;
    const int base = blockIdx.x * 128;

    float* bs  = (float*)(smem + SO_BS);
    float* bps = (float*)(smem + SO_BPS);

    const uint32_t a_off = (uint32_t)((w * 16 + (l & 15)) * 72 + (l >> 4) * 8) * 2;
    const uint32_t b_off = (uint32_t)(((l & 7) + ((l >> 4) & 1) * 8) * 72 +
                                      ((l >> 3) & 1) * 8) * 2;

    float acc[8][4];
    #pragma unroll
    for (int n = 0; n < 8; n++)
        #pragma unroll
        for (int q = 0; q < 4; q++) acc[n][q] = 0.f;

    // 4 k-tiles per half, 3 passes (A_hi*W_hi, A_hi*W_lo, A_lo*W_hi)
    auto gemm_half = [&]() {
        #pragma unroll
        for (int pass = 0; pass < 3; pass++) {
            uint32_t abase = sb + ((pass == 2) ? SO_ALO : SO_AHI);
            uint32_t bbase = sb + SO_W + ((pass == 1) ? 9216 : 0);
            #pragma unroll
            for (int kt = 0; kt < 4; kt++) {
                uint32_t af[4];
                ldsm_x4(abase + a_off + kt * 32, af);
                #pragma unroll
                for (int np = 0; np < 4; np++) {
                    uint32_t bq[4];
                    ldsm_x4(bbase + b_off + np * 2304 + kt * 32, bq);
                    mma16816(acc[2 * np],     af, bq);
                    mma16816(acc[2 * np + 1], af, bq + 2);
                }
            }
        }
    };

    // --- wave 0: W-half0 (18432B) + biases (384B) ---
    for (int i = t; i < 1152; i += 256)
        cp_async16(sb + SO_W + i * 16, g_wimg + IMG_W0 + i * 16);
    if (t < 24)
        cp_async16(sb + SO_BS + t * 16, g_wimg + IMG_BS + t * 16);
    asm volatile("cp.async.commit_group;" ::: "memory");

    // --- stage A half0 = mean (overlaps wave 0) ---
    #pragma unroll
    for (int it = 0; it < 8; it++) {
        int i = t + it * 256;
        int node = i >> 4, ch = i & 15;
        int gn = base + node;
        float4 v = make_float4(0.f, 0.f, 0.f, 0.f);
        if (gn < N) {
            v = *reinterpret_cast<const float4*>(g_agg + (long long)gn * 64 + ch * 4);
            float inv = 1.0f / fmaxf(g_deg[gn], 1.0f);
            v.x *= inv; v.y *= inv; v.z *= inv; v.w *= inv;
        }
        uint32_t h01 = pack_bf2(v.x, v.y);
        uint32_t h23 = pack_bf2(v.z, v.w);
        uint32_t l01 = pack_bf2(v.x - bf_lo(h01), v.y - bf_hi(h01));
        uint32_t l23 = pack_bf2(v.z - bf_lo(h23), v.w - bf_hi(h23));
        uint32_t off = (uint32_t)(node * 72 + ch * 4) * 2;
        *reinterpret_cast<uint2*>(smem + SO_AHI + off) = make_uint2(h01, h23);
        *reinterpret_cast<uint2*>(smem + SO_ALO + off) = make_uint2(l01, l23);
    }
    asm volatile("cp.async.wait_group 0;" ::: "memory");
    __syncthreads();

    gemm_half();          // k in [0,64): mean @ W
    __syncthreads();      // A + W slot reuse below

    // --- wave 1: W-half1 + Wp, hi/lo (27648B contiguous in image) ---
    for (int i = t; i < 1728; i += 256)
        cp_async16(sb + SO_W + i * 16, g_wimg + IMG_W1 + i * 16);
    asm volatile("cp.async.commit_group;" ::: "memory");

    // --- stage A half1 = u (overlaps wave 1) ---
    #pragma unroll
    for (int it = 0; it < 8; it++) {
        int i = t + it * 256;
        int node = i >> 4, ch = i & 15;
        int gn = base + node;
        float4 v = make_float4(0.f, 0.f, 0.f, 0.f);
        if (gn < N)
            v = *reinterpret_cast<const float4*>(u + (long long)gn * 64 + ch * 4);
        uint32_t h01 = pack_bf2(v.x, v.y);
        uint32_t h23 = pack_bf2(v.z, v.w);
        uint32_t l01 = pack_bf2(v.x - bf_lo(h01), v.y - bf_hi(h01));
        uint32_t l23 = pack_bf2(v.z - bf_lo(h23), v.w - bf_hi(h23));
        uint32_t off = (uint32_t)(node * 72 + ch * 4) * 2;
        *reinterpret_cast<uint2*>(smem + SO_AHI + off) = make_uint2(h01, h23);
        *reinterpret_cast<uint2*>(smem + SO_ALO + off) = make_uint2(l01, l23);
    }
    asm volatile("cp.async.wait_group 0;" ::: "memory");
    __syncthreads();

    gemm_half();          // k in [64,128): u @ B (accumulates)
    // No more smem writes -> no further syncs needed.

    // --- epilogue: bias+relu, store x_new, build head A-frags in regs ---
    uint32_t xh[8][2], xl[8][2];
    {
        int r0 = base + w * 16 + (l >> 2);
        #pragma unroll
        for (int n = 0; n < 8; n++) {
            int c = n * 8 + (l & 3) * 2;
            float b0 = bs[c], b1 = bs[c + 1];
            float d0 = fmaxf(acc[n][0] + b0, 0.f);
            float d1 = fmaxf(acc[n][1] + b1, 0.f);
            float d2 = fmaxf(acc[n][2] + b0, 0.f);
            float d3 = fmaxf(acc[n][3] + b1, 0.f);
            uint32_t h01 = pack_bf2(d0, d1);
            uint32_t h23 = pack_bf2(d2, d3);
            xh[n][0] = h01;
            xh[n][1] = h23;
            xl[n][0] = pack_bf2(d0 - bf_lo(h01), d1 - bf_hi(h01));
            xl[n][1] = pack_bf2(d2 - bf_lo(h23), d3 - bf_hi(h23));
            if (r0 < N)
                *reinterpret_cast<float2*>(out + (long long)r0 * 64 + c) =
                    make_float2(d0, d1);
            if (r0 + 8 < N)
                *reinterpret_cast<float2*>(out + (long long)(r0 + 8) * 64 + c) =
                    make_float2(d2, d3);
        }
    }

    // --- head GEMM: y = x_new @ Wp (+bp), 3 passes, A-frags from regs ---
    float y[4][4];
    #pragma unroll
    for (int nt = 0; nt < 4; nt++)
        #pragma unroll
        for (int q = 0; q < 4; q++) y[nt][q] = 0.f;

    const uint32_t p_off = (uint32_t)(((l & 7) + ((l >> 4) & 1) * 8) * 72 +
                                      ((l >> 3) & 1) * 8) * 2;
    const uint32_t wp_hi = sb + SO_W + 18432;
    const uint32_t wp_lo = sb + SO_W + 23040;

    auto head_pass = [&](uint32_t (*xf)[2], uint32_t pbase) {
        #pragma unroll
        for (int kk = 0; kk < 4; kk++) {
            uint32_t afr[4] = { xf[2 * kk][0], xf[2 * kk][1],
                                xf[2 * kk + 1][0], xf[2 * kk + 1][1] };
            #pragma unroll
            for (int np = 0; np < 2; np++) {
                uint32_t bq[4];
                ldsm_x4(pbase + p_off + np * 2304 + kk * 32, bq);
                mma16816(y[2 * np],     afr, bq);
                mma16816(y[2 * np + 1], afr, bq + 2);
            }
        }
    };
    head_pass(xh, wp_hi);
    head_pass(xh, wp_lo);
    head_pass(xl, wp_hi);

    {
        float* outy = out + (long long)N * 64;
        int r0 = base + w * 16 + (l >> 2);
        #pragma unroll
        for (int nt = 0; nt < 4; nt++) {
            int c = nt * 8 + (l & 3) * 2;
            float q0 = y[nt][0] + bps[c];
            float q1 = y[nt][1] + bps[c + 1];
            float q2 = y[nt][2] + bps[c];
            float q3 = y[nt][3] + bps[c + 1];
            if (r0 < N)
                *reinterpret_cast<float2*>(outy + (long long)r0 * 32 + c) =
                    make_float2(q0, q1);
            if (r0 + 8 < N)
                *reinterpret_cast<float2*>(outy + (long long)(r0 + 8) * 32 + c) =
                    make_float2(q2, q3);
        }
    }
}

// ---------------------------------------------------------------------------
extern "C" void kernel_launch(void* const* d_in, const int* in_sizes, int n_in,
                              void* d_out, int out_size)
{
    const float* x  = (const float*)d_in[0];
    const float* u  = (const float*)d_in[1];
    const void*  ei = d_in[2];
    const float* W  = (const float*)d_in[3];
    const float* B  = (const float*)d_in[4];
    const float* b  = (const float*)d_in[5];
    const float* Wp = (const float*)d_in[6];
    const float* bp = (const float*)d_in[7];
    float* out = (float*)d_out;

    int N = in_sizes[0] / 64;
    int E = in_sizes[2] / 2;

    cudaFuncSetAttribute(update_kernel,
                         cudaFuncAttributeMaxDynamicSharedMemorySize, SMEM_BYTES);

    long long nagg4 = (long long)N * 16;
    int zero_blocks = (int)((nagg4 + 255) / 256);
    prep_kernel<<<zero_blocks + 41, 256>>>(ei, E, N, zero_blocks,
                                           W, B, Wp, b, bp);

    int Q = (E + 3) / 4;
    long long sc_threads = (long long)Q * 16;
    int sc_blocks = (int)((sc_threads + 255) / 256);
    scatter_kernel<<<sc_blocks, 256>>>(x, ei, E, Q);

    int up_blocks = (N + 127) / 128;
    update_kernel<<<up_blocks, 256, SMEM_BYTES>>>(u, out, N);
}

// round 15
// speedup vs baseline: 1.0545x; 1.0545x over previous
#include <cuda_runtime.h>
#include <cuda_bf16.h>
#include <cstdint>

// ---------------------------------------------------------------------------
// RecurrentGraphNeuralNet v13 (resubmit; R14 was an infra failure):
//   prep   : fused zero(agg,deg) + dtype detect + hi/lo weight image (v12)
//   scatter: v9 4-edges/thread red.global.v4 (at LTS atomic floor)
//   update : v11 HMMA bf16 split-precision, K split in 2 halves, THREE
//            cp.async weight waves (best measured schedule), 3 blocks/SM.
// ---------------------------------------------------------------------------

#define MAXN 100000

__device__ float g_agg[(long long)MAXN * 64];
__device__ float g_deg[MAXN];
__device__ int   g_is64;

// Weight image (per-half tiles, stride 72 bf16):
// [W0hi 9216][W0lo 9216][bs 256][bps 128][pad->18816]
// [W1hi 9216][W1lo 9216][Wph 4608][Wpl 4608]   total 46464
#define IMG_W0   0
#define IMG_BS   18432
#define IMG_BPS  18688
#define IMG_W1   18816
#define IMG_WP   37248
#define IMG_BYTES 46464
__device__ __align__(128) unsigned char g_wimg[IMG_BYTES];

// ---------------------------------------------------------------------------
__device__ __forceinline__ uint32_t smem_u32(const void* p) {
    uint32_t a;
    asm("{ .reg .u64 t; cvta.to.shared.u64 t, %1; cvt.u32.u64 %0, t; }"
        : "=r"(a) : "l"(p));
    return a;
}
__device__ __forceinline__ void ldsm_x4(uint32_t addr, uint32_t r[4]) {
    asm volatile("ldmatrix.sync.aligned.m8n8.x4.shared.b16 {%0,%1,%2,%3}, [%4];"
        : "=r"(r[0]), "=r"(r[1]), "=r"(r[2]), "=r"(r[3]) : "r"(addr));
}
__device__ __forceinline__ void mma16816(float d[4], const uint32_t a[4],
                                         const uint32_t b[2]) {
    asm volatile(
        "mma.sync.aligned.m16n8k16.row.col.f32.bf16.bf16.f32 "
        "{%0,%1,%2,%3}, {%4,%5,%6,%7}, {%8,%9}, {%0,%1,%2,%3};"
        : "+f"(d[0]), "+f"(d[1]), "+f"(d[2]), "+f"(d[3])
        : "r"(a[0]), "r"(a[1]), "r"(a[2]), "r"(a[3]), "r"(b[0]), "r"(b[1]));
}
__device__ __forceinline__ void cp_async16(uint32_t dst, const void* src) {
    asm volatile("cp.async.cg.shared.global [%0], [%1], 16;"
                 :: "r"(dst), "l"(src) : "memory");
}
__device__ __forceinline__ uint32_t pack_bf2(float lo, float hi) {
    __nv_bfloat162 h = __floats2bfloat162_rn(lo, hi);
    return *reinterpret_cast<uint32_t*>(&h);
}
__device__ __forceinline__ float bf_lo(uint32_t w) {
    __nv_bfloat16 h = *reinterpret_cast<__nv_bfloat16*>(&w);
    return __bfloat162float(h);
}
__device__ __forceinline__ float bf_hi(uint32_t w) {
    uint32_t s = w >> 16;
    __nv_bfloat16 h = *reinterpret_cast<__nv_bfloat16*>(&s);
    return __bfloat162float(h);
}

// SMEM layout (bytes): A hi/lo (stride 72 bf16 = 144B rows), one streamed
// weight slot (hi+lo), biases. (v11 layout)
#define SO_AHI   0            // 18432
#define SO_ALO   18432        // 18432
#define SO_WHI   36864        // 9216 (also Wp hi in phase 2)
#define SO_WLO   46080        // 9216 (Wp lo at SO_WHI+4608)
#define SO_BS    55296        // 256
#define SO_BPS   55552        // 128
#define SMEM_BYTES 55680      // x3 blocks = 167040 <= 227KB/SM

// ---------------------------------------------------------------------------
// Fused prep: zero agg/deg, detect index dtype, build weight image.
__global__ void prep_kernel(const void* ei, int E, int N, int zero_blocks,
                            const float* __restrict__ W,
                            const float* __restrict__ Bm,
                            const float* __restrict__ Wp,
                            const float* __restrict__ b,
                            const float* __restrict__ bp)
{
    if ((int)blockIdx.x < zero_blocks) {
        long long i = (long long)blockIdx.x * 256 + threadIdx.x;
        long long nagg4 = (long long)N * 16;
        if (i < nagg4)
            *reinterpret_cast<float4*>(g_agg + i * 4) =
                make_float4(0.f, 0.f, 0.f, 0.f);
        if (i < N) g_deg[i] = 0.f;
        return;
    }
    int i = ((int)blockIdx.x - zero_blocks) * 256 + threadIdx.x;
    if (i == 0) {                         // dtype detect
        const long long* p = (const long long*)ei;
        int is64 = 1;
        #pragma unroll
        for (int k = 0; k < 8; k++) {
            long long v = p[k];
            if (v < 0 || v >= (long long)N) { is64 = 0; break; }
        }
        g_is64 = is64;
    }
    if (i < 8192) {                       // Wt[n][k], split in k-halves
        int n = i & 63, kg = i >> 6;
        float wv = (kg < 64) ? W[kg * 64 + n] : Bm[(kg - 64) * 64 + n];
        __nv_bfloat16 whi = __float2bfloat16(wv);
        __nv_bfloat16 wlo = __float2bfloat16(wv - __bfloat162float(whi));
        int half = kg >> 6, kl = kg & 63;
        uint32_t base = half ? IMG_W1 : IMG_W0;
        uint32_t off = base + (uint32_t)(n * 72 + kl) * 2;
        *reinterpret_cast<__nv_bfloat16*>(g_wimg + off)        = whi;
        *reinterpret_cast<__nv_bfloat16*>(g_wimg + off + 9216) = wlo;
    } else if (i < 10240) {               // WpT[p][k], stride 72
        int j = i - 8192;
        int p = j & 31, k = j >> 5;
        float wv = Wp[k * 32 + p];
        __nv_bfloat16 whi = __float2bfloat16(wv);
        __nv_bfloat16 wlo = __float2bfloat16(wv - __bfloat162float(whi));
        uint32_t off = IMG_WP + (uint32_t)(p * 72 + k) * 2;
        *reinterpret_cast<__nv_bfloat16*>(g_wimg + off)        = whi;
        *reinterpret_cast<__nv_bfloat16*>(g_wimg + off + 4608) = wlo;
    } else if (i < 10304) {
        int j = i - 10240;
        *reinterpret_cast<float*>(g_wimg + IMG_BS + j * 4) = b[j];
    } else if (i < 10336) {
        int j = i - 10304;
        *reinterpret_cast<float*>(g_wimg + IMG_BPS + j * 4) = bp[j];
    }
}

// ---------------------------------------------------------------------------
// Scatter (v9, at LTS atomic floor): 4 edges/thread, batched phases.
__global__ __launch_bounds__(256) void scatter_kernel(
    const float* __restrict__ x, const void* __restrict__ ei_raw, int E, int Q)
{
    long long idx = (long long)blockIdx.x * blockDim.x + threadIdx.x;
    long long total = (long long)Q * 16;
    if (idx >= total) return;

    const int is64 = g_is64;
    const int e0 = (int)(idx >> 4);
    const int f4 = ((int)idx & 15) * 4;

    int s[4], d[4];
    bool ok[4];
    #pragma unroll
    for (int j = 0; j < 4; j++) {
        int e = e0 + j * Q;
        ok[j] = (e < E);
        s[j] = 0; d[j] = 0;
        if (ok[j]) {
            if (is64) {
                const long long* ei = (const long long*)ei_raw;
                s[j] = (int)__ldg(ei + e);
                d[j] = (int)__ldg(ei + (long long)E + e);
            } else {
                const int* ei = (const int*)ei_raw;
                s[j] = __ldg(ei + e);
                d[j] = __ldg(ei + E + e);
            }
        }
    }

    float4 v[4];
    #pragma unroll
    for (int j = 0; j < 4; j++) {
        v[j] = make_float4(0.f, 0.f, 0.f, 0.f);
        if (ok[j])
            v[j] = *reinterpret_cast<const float4*>(x + (long long)s[j] * 64 + f4);
    }

    #pragma unroll
    for (int j = 0; j < 4; j++) {
        if (ok[j]) {
            float* dst = g_agg + (long long)d[j] * 64 + f4;
            asm volatile("red.global.add.v4.f32 [%0], {%1, %2, %3, %4};"
                         :: "l"(dst), "f"(v[j].x), "f"(v[j].y), "f"(v[j].z), "f"(v[j].w)
                         : "memory");
        }
    }

    if (f4 == 0) {
        #pragma unroll
        for (int j = 0; j < 4; j++)
            if (ok[j]) atomicAdd(&g_deg[d[j]], 1.0f);
    }
}

// ---------------------------------------------------------------------------
// Update (v11 verbatim): 128 nodes/block, 256 threads, 2 k-halves, 3 waves.
__global__ __launch_bounds__(256, 3) void update_kernel(
    const float* __restrict__ u, float* __restrict__ out, int N)
{
    extern __shared__ char smem[];
    const uint32_t sb = smem_u32(smem);
    const int t = threadIdx.x;
    const int l = t & 31;
    const int w = t >> 5;
    const int base = blockIdx.x * 128;

    float* bs  = (float*)(smem + SO_BS);
    float* bps = (float*)(smem + SO_BPS);

    const uint32_t a_off = (uint32_t)((w * 16 + (l & 15)) * 72 + (l >> 4) * 8) * 2;
    const uint32_t b_off = (uint32_t)(((l & 7) + ((l >> 4) & 1) * 8) * 72 +
                                      ((l >> 3) & 1) * 8) * 2;

    float acc[8][4];
    #pragma unroll
    for (int n = 0; n < 8; n++)
        #pragma unroll
        for (int q = 0; q < 4; q++) acc[n][q] = 0.f;

    // 4 k-tiles per half, 3 passes (A_hi*W_hi, A_hi*W_lo, A_lo*W_hi)
    auto gemm_half = [&]() {
        #pragma unroll
        for (int pass = 0; pass < 3; pass++) {
            uint32_t abase = sb + ((pass == 2) ? SO_ALO : SO_AHI);
            uint32_t bbase = sb + ((pass == 1) ? SO_WLO : SO_WHI);
            #pragma unroll
            for (int kt = 0; kt < 4; kt++) {
                uint32_t af[4];
                ldsm_x4(abase + a_off + kt * 32, af);
                #pragma unroll
                for (int np = 0; np < 4; np++) {
                    uint32_t bq[4];
                    ldsm_x4(bbase + b_off + np * 2304 + kt * 32, bq);
                    mma16816(acc[2 * np],     af, bq);
                    mma16816(acc[2 * np + 1], af, bq + 2);
                }
            }
        }
    };

    // --- wave 0: W-half0 + biases (18816B) ---
    for (int i = t; i < 1176; i += 256)
        cp_async16(sb + SO_WHI + i * 16, g_wimg + IMG_W0 + i * 16);
    asm volatile("cp.async.commit_group;" ::: "memory");

    // --- stage A half0 = mean (overlaps wave 0) ---
    #pragma unroll
    for (int it = 0; it < 8; it++) {
        int i = t + it * 256;
        int node = i >> 4, ch = i & 15;
        int gn = base + node;
        float4 v = make_float4(0.f, 0.f, 0.f, 0.f);
        if (gn < N) {
            v = *reinterpret_cast<const float4*>(g_agg + (long long)gn * 64 + ch * 4);
            float inv = 1.0f / fmaxf(g_deg[gn], 1.0f);
            v.x *= inv; v.y *= inv; v.z *= inv; v.w *= inv;
        }
        uint32_t h01 = pack_bf2(v.x, v.y);
        uint32_t h23 = pack_bf2(v.z, v.w);
        uint32_t l01 = pack_bf2(v.x - bf_lo(h01), v.y - bf_hi(h01));
        uint32_t l23 = pack_bf2(v.z - bf_lo(h23), v.w - bf_hi(h23));
        uint32_t off = (uint32_t)(node * 72 + ch * 4) * 2;
        *reinterpret_cast<uint2*>(smem + SO_AHI + off) = make_uint2(h01, h23);
        *reinterpret_cast<uint2*>(smem + SO_ALO + off) = make_uint2(l01, l23);
    }
    asm volatile("cp.async.wait_group 0;" ::: "memory");
    __syncthreads();

    gemm_half();          // k in [0,64): mean @ W
    __syncthreads();

    // --- wave 1: W-half1 (18432B) ---
    for (int i = t; i < 1152; i += 256)
        cp_async16(sb + SO_WHI + i * 16, g_wimg + IMG_W1 + i * 16);
    asm volatile("cp.async.commit_group;" ::: "memory");

    // --- stage A half1 = u (overlaps wave 1) ---
    #pragma unroll
    for (int it = 0; it < 8; it++) {
        int i = t + it * 256;
        int node = i >> 4, ch = i & 15;
        int gn = base + node;
        float4 v = make_float4(0.f, 0.f, 0.f, 0.f);
        if (gn < N)
            v = *reinterpret_cast<const float4*>(u + (long long)gn * 64 + ch * 4);
        uint32_t h01 = pack_bf2(v.x, v.y);
        uint32_t h23 = pack_bf2(v.z, v.w);
        uint32_t l01 = pack_bf2(v.x - bf_lo(h01), v.y - bf_hi(h01));
        uint32_t l23 = pack_bf2(v.z - bf_lo(h23), v.w - bf_hi(h23));
        uint32_t off = (uint32_t)(node * 72 + ch * 4) * 2;
        *reinterpret_cast<uint2*>(smem + SO_AHI + off) = make_uint2(h01, h23);
        *reinterpret_cast<uint2*>(smem + SO_ALO + off) = make_uint2(l01, l23);
    }
    asm volatile("cp.async.wait_group 0;" ::: "memory");
    __syncthreads();

    gemm_half();          // k in [64,128): u @ B (accumulates)
    __syncthreads();      // weight slot free for Wp

    // --- wave 2: Wp hi+lo (9216B) into the weight slot ---
    for (int i = t; i < 576; i += 256)
        cp_async16(sb + SO_WHI + i * 16, g_wimg + IMG_WP + i * 16);
    asm volatile("cp.async.commit_group;" ::: "memory");

    // --- epilogue (overlaps wave 2): bias+relu, store x_new, build frags ---
    uint32_t xh[8][2], xl[8][2];
    {
        int r0 = base + w * 16 + (l >> 2);
        #pragma unroll
        for (int n = 0; n < 8; n++) {
            int c = n * 8 + (l & 3) * 2;
            float b0 = bs[c], b1 = bs[c + 1];
            float d0 = fmaxf(acc[n][0] + b0, 0.f);
            float d1 = fmaxf(acc[n][1] + b1, 0.f);
            float d2 = fmaxf(acc[n][2] + b0, 0.f);
            float d3 = fmaxf(acc[n][3] + b1, 0.f);
            uint32_t h01 = pack_bf2(d0, d1);
            uint32_t h23 = pack_bf2(d2, d3);
            xh[n][0] = h01;
            xh[n][1] = h23;
            xl[n][0] = pack_bf2(d0 - bf_lo(h01), d1 - bf_hi(h01));
            xl[n][1] = pack_bf2(d2 - bf_lo(h23), d3 - bf_hi(h23));
            if (r0 < N)
                *reinterpret_cast<float2*>(out + (long long)r0 * 64 + c) =
                    make_float2(d0, d1);
            if (r0 + 8 < N)
                *reinterpret_cast<float2*>(out + (long long)(r0 + 8) * 64 + c) =
                    make_float2(d2, d3);
        }
    }
    asm volatile("cp.async.wait_group 0;" ::: "memory");
    __syncthreads();

    // --- head GEMM: y = x_new @ Wp (+bp), 3 passes, A-frags from regs ---
    float y[4][4];
    #pragma unroll
    for (int nt = 0; nt < 4; nt++)
        #pragma unroll
        for (int q = 0; q < 4; q++) y[nt][q] = 0.f;

    const uint32_t p_off = (uint32_t)(((l & 7) + ((l >> 4) & 1) * 8) * 72 +
                                      ((l >> 3) & 1) * 8) * 2;

    auto head_pass = [&](uint32_t (*xf)[2], uint32_t pbase) {
        #pragma unroll
        for (int kk = 0; kk < 4; kk++) {
            uint32_t afr[4] = { xf[2 * kk][0], xf[2 * kk][1],
                                xf[2 * kk + 1][0], xf[2 * kk + 1][1] };
            #pragma unroll
            for (int np = 0; np < 2; np++) {
                uint32_t bq[4];
                ldsm_x4(pbase + p_off + np * 2304 + kk * 32, bq);
                mma16816(y[2 * np],     afr, bq);
                mma16816(y[2 * np + 1], afr, bq + 2);
            }
        }
    };
    head_pass(xh, sb + SO_WHI);           // hi x Wp_hi
    head_pass(xh, sb + SO_WHI + 4608);    // hi x Wp_lo
    head_pass(xl, sb + SO_WHI);           // lo x Wp_hi

    {
        float* outy = out + (long long)N * 64;
        int r0 = base + w * 16 + (l >> 2);
        #pragma unroll
        for (int nt = 0; nt < 4; nt++) {
            int c = nt * 8 + (l & 3) * 2;
            float q0 = y[nt][0] + bps[c];
            float q1 = y[nt][1] + bps[c + 1];
            float q2 = y[nt][2] + bps[c];
            float q3 = y[nt][3] + bps[c + 1];
            if (r0 < N)
                *reinterpret_cast<float2*>(outy + (long long)r0 * 32 + c) =
                    make_float2(q0, q1);
            if (r0 + 8 < N)
                *reinterpret_cast<float2*>(outy + (long long)(r0 + 8) * 32 + c) =
                    make_float2(q2, q3);
        }
    }
}

// ---------------------------------------------------------------------------
extern "C" void kernel_launch(void* const* d_in, const int* in_sizes, int n_in,
                              void* d_out, int out_size)
{
    const float* x  = (const float*)d_in[0];
    const float* u  = (const float*)d_in[1];
    const void*  ei = d_in[2];
    const float* W  = (const float*)d_in[3];
    const float* B  = (const float*)d_in[4];
    const float* b  = (const float*)d_in[5];
    const float* Wp = (const float*)d_in[6];
    const float* bp = (const float*)d_in[7];
    float* out = (float*)d_out;

    int N = in_sizes[0] / 64;
    int E = in_sizes[2] / 2;

    cudaFuncSetAttribute(update_kernel,
                         cudaFuncAttributeMaxDynamicSharedMemorySize, SMEM_BYTES);

    long long nagg4 = (long long)N * 16;
    int zero_blocks = (int)((nagg4 + 255) / 256);
    prep_kernel<<<zero_blocks + 41, 256>>>(ei, E, N, zero_blocks,
                                           W, B, Wp, b, bp);

    int Q = (E + 3) / 4;
    long long sc_threads = (long long)Q * 16;
    int sc_blocks = (int)((sc_threads + 255) / 256);
    scatter_kernel<<<sc_blocks, 256>>>(x, ei, E, Q);

    int up_blocks = (N + 127) / 128;
    update_kernel<<<up_blocks, 256, SMEM_BYTES>>>(u, out, N);
}